// round 4
// baseline (speedup 1.0000x reference)
#include <cuda_runtime.h>
#include <stdint.h>

// ---------------- problem constants ----------------
// SPARSE_SHAPE (468,468,1), WINDOW (12,12,1), BATCH 4
// _NX=_NY=40, _NZ=2 ; win_z==0 always ; full_win = 2*compact
// compact win id = b*1600 + wx*40 + wy  in [0, 6400)
#define NWc     6400
#define CH      512
#define WAVES   16              // CH / 32
#define NB_MAX  640
#define MAXN    (NB_MAX * CH)   // 327680
#define FULLM   0xFFFFFFFFu

// ---------------- static scratch (no allocations; zero-initialized at load) --
__device__ int           g_H[NB_MAX * NWc];   // per-chunk exclusive offsets (kept zeroed between launches)
__device__ int           g_winc0[MAXN];
__device__ int           g_winc1[MAXN];
__device__ int           g_inner0[MAXN];
__device__ int           g_inner1[MAXN];
__device__ unsigned char g_keep0[MAXN];
__device__ unsigned char g_keepF[MAXN];
__device__ int           g_counts0[NWc];
__device__ int           g_counts1[NWc];

__device__ __forceinline__ void lvl_target(int n, int& lvl, int& target) {
    if (n < 16)      { lvl = 0; target = 16; }
    else if (n < 32) { lvl = 1; target = 32; }
    else if (n < 64) { lvl = 2; target = 64; }
    else             { lvl = 3; target = 144; }
}

// ---------------- phase 1a: window ids + chunk histogram (round 0) ----------
__global__ void k_hist0(const int* __restrict__ coords, int N) {
    int c = blockIdx.x;
    int base = c * CH;
    for (int t = threadIdx.x; t < CH; t += blockDim.x) {
        int idx = base + t;
        if (idx < N) {
            int4 cc = ((const int4*)coords)[idx];        // (b,z,y,x)
            int b = cc.x, y = cc.z, x = cc.w;
            int w0 = b * 1600 + ((x + 12) / 12) * 40 + ((y + 12) / 12);
            int w1 = b * 1600 + ((x + 6)  / 12) * 40 + ((y + 6)  / 12);
            g_winc0[idx] = w0;
            g_winc1[idx] = w1;
            atomicAdd(&g_H[c * NWc + w0], 1);
        }
    }
}

// ---------------- phase 1b: chunk histogram round 1 (masked by keep0) -------
__global__ void k_hist1(int N) {
    int c = blockIdx.x;
    int base = c * CH;
    for (int t = threadIdx.x; t < CH; t += blockDim.x) {
        int idx = base + t;
        if (idx < N && g_keep0[idx]) {
            atomicAdd(&g_H[c * NWc + g_winc1[idx]], 1);
        }
    }
}

// ---------------- phase 2: per-window exclusive scan over chunks ------------
__global__ void k_scan(int* __restrict__ counts, int NB) {
    int w = blockIdx.x * blockDim.x + threadIdx.x;
    if (w >= NWc) return;
    int run = 0;
#pragma unroll 16
    for (int c = 0; c < NB; c++) {
        int* p = &g_H[c * NWc + w];
        int h = *p;
        *p = run;       // exclusive prefix: base offset for chunk c
        run += h;
    }
    counts[w] = run;
}

// ---------------- phase 3: stable rank via ordered atomic claims ------------
// One warp per 512-voxel chunk. No smem table: the wave leader claims slots
// with atomicAdd on g_H (whose value is the current exclusive offset). Waves
// are serialized by threading the previous wave's base into the next atomic's
// address ((dep >> 31) == 0 but opaque), guaranteeing stable index order when
// the same window recurs across waves. Afterwards each block zeroes its own
// g_H region, restoring the all-zero invariant for the next histogram pass.
__global__ void __launch_bounds__(32)
k_rank(const int* __restrict__ winc, const unsigned char* __restrict__ keepIn,
       const int* __restrict__ counts,
       int* __restrict__ innerOut, unsigned char* __restrict__ keepOut, int N) {
    int c = blockIdx.x;
    int lane = threadIdx.x;
    int base0 = c * CH;
    int* Hrow = &g_H[c * NWc];

    // prefetch window ids, keep flags (bitmask), drop targets (2b levels)
    int wv[WAVES];
    unsigned kvm = 0;      // bit s: this lane's voxel in wave s is kept-in
    unsigned lvp = 0;      // 2 bits per wave: drop level of this voxel's window
#pragma unroll
    for (int s = 0; s < WAVES; s++) {
        int idx = base0 + s * 32 + lane;
        int act = idx < N;
        wv[s] = act ? __ldg(&winc[idx]) : 0;
        int k = act ? (keepIn ? (int)keepIn[idx] : 1) : 0;
        kvm |= (unsigned)k << s;
    }
#pragma unroll
    for (int s = 0; s < WAVES; s++) {
        if ((kvm >> s) & 1) {
            int cnt = __ldg(&counts[wv[s]]);
            int lvl = (cnt < 16) ? 0 : (cnt < 32) ? 1 : (cnt < 64) ? 2 : 3;
            lvp |= (unsigned)lvl << (2 * s);
        }
    }

    unsigned ltmask = (1u << lane) - 1u;
    int dep = 0;   // carries previous wave's base: serializes same-window atomics
#pragma unroll
    for (int s = 0; s < WAVES; s++) {
        int k = (kvm >> s) & 1;
        unsigned kmask = __ballot_sync(FULLM, k);
        unsigned peers = __match_any_sync(FULLM, wv[s]) & kmask;
        int leader = __ffs((int)peers) - 1;     // -1 if nobody kept in group
        int base = 0;
        if (k && lane == leader) {
            // (dep >> 31) is always 0 (offsets are non-negative) but forces the
            // address to depend on the previous wave's atomic return value.
            base = atomicAdd(&Hrow[wv[s] + (dep >> 31)], __popc(peers));
        }
        base = __shfl_sync(FULLM, base, leader < 0 ? 0 : leader);
        dep = base;
        int idx = base0 + s * 32 + lane;
        if (idx < N) {
            int inner = k ? (base + __popc(peers & ltmask)) : -1;
            innerOut[idx] = inner;
            int tgt = (int)((0x90402010u >> (8 * ((lvp >> (2 * s)) & 3))) & 0xFFu);
            keepOut[idx] = (k && inner < tgt) ? 1 : 0;
        }
    }

    // restore the all-zero invariant for this block's g_H region
    __syncwarp();
    int4 z4 = make_int4(0, 0, 0, 0);
    int4* Hv = (int4*)Hrow;
#pragma unroll
    for (int t = lane; t < NWc / 4; t += 32)
        Hv[t] = z4;
}

// ---------------- phase 4a: scalar output vectors ---------------------------
__global__ void k_outvec(float* __restrict__ out, int N,
                         size_t off_keep, size_t off_w0, size_t off_w1,
                         size_t off_dl0, size_t off_dl1,
                         size_t off_i0, size_t off_i1) {
    for (int i = blockIdx.x * blockDim.x + threadIdx.x; i < N; i += gridDim.x * blockDim.x) {
        int w0 = g_winc0[i], w1 = g_winc1[i];
        out[off_keep + i] = g_keepF[i] ? 1.0f : 0.0f;
        out[off_w0 + i]   = (float)(2 * w0);
        out[off_w1 + i]   = (float)(2 * w1);
        int l0, t0; lvl_target(g_counts0[w0], l0, t0);
        out[off_dl0 + i] = (float)l0;
        float dl1 = -1.0f;
        if (g_keep0[i]) {
            int l1, t1; lvl_target(g_counts1[w1], l1, t1);
            dl1 = (float)l1;
        }
        out[off_dl1 + i] = dl1;
        out[off_i0 + i] = (float)g_inner0[i];
        out[off_i1 + i] = (float)g_inner1[i];
    }
}

// ---------------- phase 4b: masked features + positional embeddings ---------
__global__ void __launch_bounds__(128)
k_outfeat(const float* __restrict__ feat, const int* __restrict__ coords,
          float* __restrict__ out, int N, int C,
          size_t off_pe0, size_t off_pe1) {
    int cidx = threadIdx.x;           // 0..C-1 (C=128)
    int half = C >> 1;                // 64
    bool isy = cidx >= half;
    int j = (isy ? (cidx - half) : cidx) >> 1;        // freq index 0..31
    bool iscos = (cidx & 1);
    // 1/inv_freq = 10000^(-(2j)/(C/2)) = 2^(-j * 4*log2(1e4)/C)
    float rec = exp2f(-(float)j * (13.28771237954944987f * 4.0f / (float)C));

    for (int i = blockIdx.x; i < N; i += gridDim.x) {
        int x = __ldg(&coords[i * 4 + 3]);
        int y = __ldg(&coords[i * 4 + 2]);
        float kf = g_keepF[i] ? 1.0f : 0.0f;
        size_t row = (size_t)i * C + cidx;
        out[row] = feat[row] * kf;

        int v = isy ? y : x;
        float v0 = (float)(v % 12) - 6.0f;            // unshifted in-window coord - w/2
        float v1 = (float)((v + 6) % 12) - 6.0f;      // shifted
        float a0 = v0 * rec, a1 = v1 * rec;
        out[off_pe0 + row] = iscos ? __cosf(a0) : __sinf(a0);
        out[off_pe1 + row] = iscos ? __cosf(a1) : __sinf(a1);
    }
}

// ---------------- launch ----------------
extern "C" void kernel_launch(void* const* d_in, const int* in_sizes, int n_in,
                              void* d_out, int out_size) {
    const float* feat   = (const float*)d_in[0];
    const int*   coords = (const int*)d_in[1];
    int N = in_sizes[1] / 4;
    int C = in_sizes[0] / N;          // 128
    if (N > MAXN) N = MAXN;           // safety (setup gives exactly 300000)
    int NB = (N + CH - 1) / CH;       // 586

    float* out = (float*)d_out;
    size_t Ns = (size_t)N, Cs = (size_t)C;
    size_t off = Ns * Cs;             // feat at 0
    size_t off_keep = off; off += Ns;
    size_t off_w0   = off; off += Ns;
    size_t off_w1   = off; off += Ns;
    size_t off_dl0  = off; off += Ns;
    size_t off_dl1  = off; off += Ns;
    size_t off_i0   = off; off += Ns;
    size_t off_i1   = off; off += Ns;
    size_t off_pe0  = off; off += Ns * Cs;
    size_t off_pe1  = off;

    int* dC0 = nullptr; cudaGetSymbolAddress((void**)&dC0, g_counts0);
    int* dC1 = nullptr; cudaGetSymbolAddress((void**)&dC1, g_counts1);
    int* dW0 = nullptr; cudaGetSymbolAddress((void**)&dW0, g_winc0);
    int* dW1 = nullptr; cudaGetSymbolAddress((void**)&dW1, g_winc1);
    int* dI0 = nullptr; cudaGetSymbolAddress((void**)&dI0, g_inner0);
    int* dI1 = nullptr; cudaGetSymbolAddress((void**)&dI1, g_inner1);
    unsigned char* dK0 = nullptr; cudaGetSymbolAddress((void**)&dK0, g_keep0);
    unsigned char* dKF = nullptr; cudaGetSymbolAddress((void**)&dKF, g_keepF);

    // g_H is all-zero on entry: zero-initialized at load, and every k_rank
    // block re-zeroes its own region after consuming it.

    // ---- round 0 (unshifted windows, keep = all) ----
    k_hist0<<<NB, 256>>>(coords, N);
    k_scan<<<(NWc + 255) / 256, 256>>>(dC0, NB);
    k_rank<<<NB, 32>>>(dW0, nullptr, dC0, dI0, dK0, N);

    // ---- round 1 (shifted windows, keep = keep0) ----
    k_hist1<<<NB, 256>>>(N);
    k_scan<<<(NWc + 255) / 256, 256>>>(dC1, NB);
    k_rank<<<NB, 32>>>(dW1, dK0, dC1, dI1, dKF, N);

    // ---- outputs ----
    k_outvec<<<512, 256>>>(out, N, off_keep, off_w0, off_w1,
                           off_dl0, off_dl1, off_i0, off_i1);
    k_outfeat<<<2368, 128>>>(feat, coords, out, N, C, off_pe0, off_pe1);
}

// round 5
// speedup vs baseline: 1.5242x; 1.5242x over previous
#include <cuda_runtime.h>
#include <stdint.h>

// ---------------- problem constants ----------------
// SPARSE_SHAPE (468,468,1), WINDOW (12,12,1), BATCH 4
// _NX=_NY=40, _NZ=2 ; win_z==0 always ; full_win = 2*compact
// compact win id = b*1600 + wx*40 + wy  in [0, 6400)
#define NWc   6400
#define CAP   512               // max voxels per window (uniform data: ~49 mean)
#define MAXN  327680
#define FULLM 0xFFFFFFFFu

// ---------------- static scratch (no allocations allowed) -------------------
__device__ int           g_cnt0[NWc];
__device__ int           g_cnt1[NWc];
__device__ int           g_bkt0[NWc * CAP];   // voxel indices per window, round 0
__device__ int           g_bkt1[NWc * CAP];   // round 1
__device__ int           g_winc0[MAXN];
__device__ int           g_winc1[MAXN];
__device__ int           g_inner0[MAXN];
__device__ int           g_inner1[MAXN];
__device__ unsigned char g_keep0[MAXN];
__device__ unsigned char g_keepF[MAXN];

__device__ __forceinline__ void lvl_target(int n, int& lvl, int& target) {
    if (n < 16)      { lvl = 0; target = 16; }
    else if (n < 32) { lvl = 1; target = 32; }
    else if (n < 64) { lvl = 2; target = 64; }
    else             { lvl = 3; target = 144; }
}

// ---------------- phase 0: zero the 2x6400 window counters ------------------
__global__ void k_zerocnt() {
    int i = blockIdx.x * blockDim.x + threadIdx.x;
    if (i < NWc) { g_cnt0[i] = 0; g_cnt1[i] = 0; }
}

// ---------------- phase 1: window ids + bucket scatter (round 0) ------------
__global__ void k_scatter0(const int* __restrict__ coords, int N) {
    for (int i = blockIdx.x * blockDim.x + threadIdx.x; i < N;
         i += gridDim.x * blockDim.x) {
        int4 cc = ((const int4*)coords)[i];          // (b,z,y,x)
        int b = cc.x, y = cc.z, x = cc.w;
        int w0 = b * 1600 + ((x + 12) / 12) * 40 + ((y + 12) / 12);
        int w1 = b * 1600 + ((x + 6)  / 12) * 40 + ((y + 6)  / 12);
        g_winc0[i] = w0;
        g_winc1[i] = w1;
        int pos = atomicAdd(&g_cnt0[w0], 1);
        if (pos < CAP) g_bkt0[w0 * CAP + pos] = i;
    }
}

// ---------------- phase 2: per-window stable rank (round 0) -----------------
// rank of element = number of bucket entries with smaller voxel index.
__global__ void __launch_bounds__(128)
k_wrank0() {
    __shared__ int s[CAP];
    int w = blockIdx.x;
    int n = g_cnt0[w];
    if (n > CAP) n = CAP;
    for (int t = threadIdx.x; t < n; t += 128) s[t] = g_bkt0[w * CAP + t];
    __syncthreads();
    int lvl, target; lvl_target(n, lvl, target);
    for (int e = threadIdx.x; e < n; e += 128) {
        int my = s[e];
        int r = 0;
        for (int j = 0; j < n; j++) r += (s[j] < my);
        g_inner0[my] = r;
        g_keep0[my]  = (r < target) ? 1 : 0;
    }
}

// ---------------- phase 3: bucket scatter (round 1, masked) -----------------
__global__ void k_scatter1(int N) {
    for (int i = blockIdx.x * blockDim.x + threadIdx.x; i < N;
         i += gridDim.x * blockDim.x) {
        if (g_keep0[i]) {
            int w1 = g_winc1[i];
            int pos = atomicAdd(&g_cnt1[w1], 1);
            if (pos < CAP) g_bkt1[w1 * CAP + pos] = i;
        } else {
            g_inner1[i] = -1;
            g_keepF[i]  = 0;
        }
    }
}

// ---------------- phase 4: per-window stable rank (round 1) -----------------
__global__ void __launch_bounds__(128)
k_wrank1() {
    __shared__ int s[CAP];
    int w = blockIdx.x;
    int n = g_cnt1[w];
    if (n > CAP) n = CAP;
    for (int t = threadIdx.x; t < n; t += 128) s[t] = g_bkt1[w * CAP + t];
    __syncthreads();
    int lvl, target; lvl_target(n, lvl, target);
    for (int e = threadIdx.x; e < n; e += 128) {
        int my = s[e];
        int r = 0;
        for (int j = 0; j < n; j++) r += (s[j] < my);
        g_inner1[my] = r;
        g_keepF[my]  = (r < target) ? 1 : 0;
    }
}

// ---------------- phase 5a: scalar output vectors ---------------------------
__global__ void k_outvec(float* __restrict__ out, int N,
                         size_t off_keep, size_t off_w0, size_t off_w1,
                         size_t off_dl0, size_t off_dl1,
                         size_t off_i0, size_t off_i1) {
    for (int i = blockIdx.x * blockDim.x + threadIdx.x; i < N;
         i += gridDim.x * blockDim.x) {
        int w0 = g_winc0[i], w1 = g_winc1[i];
        out[off_keep + i] = g_keepF[i] ? 1.0f : 0.0f;
        out[off_w0 + i]   = (float)(2 * w0);
        out[off_w1 + i]   = (float)(2 * w1);
        int l0, t0; lvl_target(g_cnt0[w0], l0, t0);
        out[off_dl0 + i] = (float)l0;
        float dl1 = -1.0f;
        if (g_keep0[i]) {
            int l1, t1; lvl_target(g_cnt1[w1], l1, t1);
            dl1 = (float)l1;
        }
        out[off_dl1 + i] = dl1;
        out[off_i0 + i] = (float)g_inner0[i];
        out[off_i1 + i] = (float)g_inner1[i];
    }
}

// ---------------- phase 5b: masked features + positional embeddings ---------
__global__ void __launch_bounds__(128)
k_outfeat(const float* __restrict__ feat, const int* __restrict__ coords,
          float* __restrict__ out, int N, int C,
          size_t off_pe0, size_t off_pe1) {
    int cidx = threadIdx.x;           // 0..C-1 (C=128)
    int half = C >> 1;                // 64
    bool isy = cidx >= half;
    int j = (isy ? (cidx - half) : cidx) >> 1;        // freq index 0..31
    bool iscos = (cidx & 1);
    // 1/inv_freq = 10000^(-(2j)/(C/2)) = 2^(-j * 4*log2(1e4)/C)
    float rec = exp2f(-(float)j * (13.28771237954944987f * 4.0f / (float)C));

    for (int i = blockIdx.x; i < N; i += gridDim.x) {
        int x = __ldg(&coords[i * 4 + 3]);
        int y = __ldg(&coords[i * 4 + 2]);
        float kf = g_keepF[i] ? 1.0f : 0.0f;
        size_t row = (size_t)i * C + cidx;
        out[row] = feat[row] * kf;

        int v = isy ? y : x;
        float v0 = (float)(v % 12) - 6.0f;            // unshifted in-window coord - w/2
        float v1 = (float)((v + 6) % 12) - 6.0f;      // shifted
        float a0 = v0 * rec, a1 = v1 * rec;
        out[off_pe0 + row] = iscos ? __cosf(a0) : __sinf(a0);
        out[off_pe1 + row] = iscos ? __cosf(a1) : __sinf(a1);
    }
}

// ---------------- launch ----------------
extern "C" void kernel_launch(void* const* d_in, const int* in_sizes, int n_in,
                              void* d_out, int out_size) {
    const float* feat   = (const float*)d_in[0];
    const int*   coords = (const int*)d_in[1];
    int N = in_sizes[1] / 4;
    int C = in_sizes[0] / N;          // 128
    if (N > MAXN) N = MAXN;           // safety (setup gives exactly 300000)

    float* out = (float*)d_out;
    size_t Ns = (size_t)N, Cs = (size_t)C;
    size_t off = Ns * Cs;             // feat at 0
    size_t off_keep = off; off += Ns;
    size_t off_w0   = off; off += Ns;
    size_t off_w1   = off; off += Ns;
    size_t off_dl0  = off; off += Ns;
    size_t off_dl1  = off; off += Ns;
    size_t off_i0   = off; off += Ns;
    size_t off_i1   = off; off += Ns;
    size_t off_pe0  = off; off += Ns * Cs;
    size_t off_pe1  = off;

    k_zerocnt<<<(NWc + 255) / 256, 256>>>();
    k_scatter0<<<592, 256>>>(coords, N);
    k_wrank0<<<NWc, 128>>>();
    k_scatter1<<<592, 256>>>(N);
    k_wrank1<<<NWc, 128>>>();
    k_outvec<<<512, 256>>>(out, N, off_keep, off_w0, off_w1,
                           off_dl0, off_dl1, off_i0, off_i1);
    k_outfeat<<<2368, 128>>>(feat, coords, out, N, C, off_pe0, off_pe1);
}